// round 2
// baseline (speedup 1.0000x reference)
#include <cuda_runtime.h>
#include <math_constants.h>

#define B_ 8
#define N_ 2048
#define C_ 64
#define K_ 32
#define W_COLS 67   // C + 3

// Scratch (allocation-free rule: device globals)
__device__ __align__(16) float g_Gt[B_*N_*C_];   // (b, n, o): inv[o] * (W_f @ feats)[o,n]
__device__ int g_idx[B_*N_*K_];

// ---------------------------------------------------------------------------
// Kernel A: Gt[b][n][o] = inv[o] * sum_c conv_w[o][3+c] * feats[b][c][n]
// ---------------------------------------------------------------------------
__global__ __launch_bounds__(256) void kA(const float* __restrict__ feats,
                                          const float* __restrict__ conv_w,
                                          const float* __restrict__ gamma,
                                          const float* __restrict__ var) {
    __shared__ float sW[C_][C_];   // [c][o], BN-scaled
    __shared__ float sF[C_][64];   // [c][n]
    int b  = blockIdx.x;
    int n0 = blockIdx.y * 64;
    int t  = threadIdx.x;

    for (int x = t; x < C_*C_; x += 256) {
        int o = x & 63, c = x >> 6;
        float inv = gamma[o] * rsqrtf(var[o] + 1e-5f);
        sW[c][o] = conv_w[o*W_COLS + 3 + c] * inv;
    }
    for (int x = t; x < C_*64; x += 256) {
        int c = x >> 6, n = x & 63;
        sF[c][n] = feats[(b*C_ + c)*N_ + n0 + n];
    }
    __syncthreads();

    int oT = (t & 15) * 4;   // 16 o-tiles of 4
    int nT = (t >> 4) * 4;   // 16 n-tiles of 4
    float acc[4][4] = {};
    #pragma unroll 8
    for (int c = 0; c < C_; c++) {
        float w0 = sW[c][oT+0], w1 = sW[c][oT+1], w2 = sW[c][oT+2], w3 = sW[c][oT+3];
        #pragma unroll
        for (int j = 0; j < 4; j++) {
            float f = sF[c][nT+j];
            acc[j][0] = fmaf(w0, f, acc[j][0]);
            acc[j][1] = fmaf(w1, f, acc[j][1]);
            acc[j][2] = fmaf(w2, f, acc[j][2]);
            acc[j][3] = fmaf(w3, f, acc[j][3]);
        }
    }
    #pragma unroll
    for (int j = 0; j < 4; j++) {
        float4 v = make_float4(acc[j][0], acc[j][1], acc[j][2], acc[j][3]);
        *reinterpret_cast<float4*>(&g_Gt[((b*N_) + n0 + nT + j)*C_ + oT]) = v;
    }
}

// ---------------------------------------------------------------------------
// Kernel B: exact kNN (K=32) per query, warp-per-query.
// Distance computed to REPLICATE the reference cdist rounding:
//   sq   = ((x*x + y*y) + z*z)                (plain mul/add, no fma)
//   dot  = fma(z, z', fma(y, y', x*x'))       (ascending-k fma chain, gemm-style)
//   d2   = max((sq_i + sq_j) - 2*dot, 0)
// Tie-break: lexicographic (d2, idx) ascending -> matches stable top_k.
// ---------------------------------------------------------------------------
__global__ __launch_bounds__(512) void kB(const float* __restrict__ coords) {
    __shared__ float4 sC[N_];   // 32 KB: coords + precomputed sq in .w
    int t = threadIdx.x;
    int warp = t >> 5, lane = t & 31;
    int b = blockIdx.x >> 7;                       // 128 blocks per batch
    int i = ((blockIdx.x & 127) << 4) + warp;      // query index

    for (int x = t; x < N_; x += 512) {
        const float* c = coords + (b*N_ + x)*3;
        float cx = c[0], cy = c[1], cz = c[2];
        float sq = __fadd_rn(__fadd_rn(__fmul_rn(cx,cx), __fmul_rn(cy,cy)),
                             __fmul_rn(cz,cz));
        sC[x] = make_float4(cx, cy, cz, sq);
    }
    __syncthreads();

    float4 q = sC[i];

    // reference-matched squared distance
    auto refd2 = [&](const float4& p) -> float {
        float dot = __fmaf_rn(q.z, p.z, __fmaf_rn(q.y, p.y, __fmul_rn(q.x, p.x)));
        float d2  = __fsub_rn(__fadd_rn(q.w, p.w), __fmul_rn(2.0f, dot));
        return fmaxf(d2, 0.0f);
    };

    // init set with first 32 candidates
    float bd = refd2(sC[lane]);   // this lane's set element
    int   bi = lane;

    // warp arg-max of (bd, bi): all lanes end with identical (md, mi, ml)
    float md = bd; int mi = bi; int ml = lane;
    #pragma unroll
    for (int off = 16; off; off >>= 1) {
        float od = __shfl_xor_sync(0xffffffffu, md, off);
        int   oi = __shfl_xor_sync(0xffffffffu, mi, off);
        int   ol = __shfl_xor_sync(0xffffffffu, ml, off);
        if (od > md || (od == md && oi > mi)) { md = od; mi = oi; ml = ol; }
    }

    for (int tt = 32; tt < N_; tt += 32) {
        int j = tt + lane;
        float d2 = refd2(sC[j]);
        bool beat = (d2 < md) || (d2 == md && j < mi);
        unsigned m = __ballot_sync(0xffffffffu, beat);
        while (m) {   // serial insertion; loop + inner branch are warp-uniform
            int src = __ffs(m) - 1;
            m &= m - 1;
            float cd = __shfl_sync(0xffffffffu, d2, src);
            int   cj = tt + src;
            if (cd < md || (cd == md && cj < mi)) {
                if (lane == ml) { bd = cd; bi = cj; }   // evict current max
                md = bd; mi = bi; ml = lane;
                #pragma unroll
                for (int off = 16; off; off >>= 1) {
                    float od = __shfl_xor_sync(0xffffffffu, md, off);
                    int   oi = __shfl_xor_sync(0xffffffffu, mi, off);
                    int   ol = __shfl_xor_sync(0xffffffffu, ml, off);
                    if (od > md || (od == md && oi > mi)) { md = od; mi = oi; ml = ol; }
                }
            }
        }
    }
    g_idx[(b*N_ + i)*K_ + lane] = bi;
}

// ---------------------------------------------------------------------------
// Kernel C: per point (warp-per-point):
//   rel_k = (coords[idx_k] - coords[i]) / R
//   density: 16th-smallest pairwise dist among the 32 grouped points
//   out[o,i] = sum_k w_k * relu(Gt[idx_k][o] + Wrel'[o]·rel_k + bias'[o])
// ---------------------------------------------------------------------------
__global__ __launch_bounds__(256) void kC(const float* __restrict__ coords,
                                          const float* __restrict__ conv_w,
                                          const float* __restrict__ gamma,
                                          const float* __restrict__ beta,
                                          const float* __restrict__ mean,
                                          const float* __restrict__ var,
                                          float* __restrict__ out) {
    int t = threadIdx.x;
    int warp = t >> 5, lane = t & 31;
    int pidx = blockIdx.x * 8 + warp;
    int b = pidx >> 11;
    int i = pidx & (N_ - 1);

    // per-lane channel constants (o0 = lane, o1 = lane + 32), BN folded
    int o0 = lane, o1 = lane + 32;
    float inv0 = gamma[o0] * rsqrtf(var[o0] + 1e-5f);
    float inv1 = gamma[o1] * rsqrtf(var[o1] + 1e-5f);
    float w0x = conv_w[o0*W_COLS+0]*inv0, w0y = conv_w[o0*W_COLS+1]*inv0, w0z = conv_w[o0*W_COLS+2]*inv0;
    float w1x = conv_w[o1*W_COLS+0]*inv1, w1y = conv_w[o1*W_COLS+1]*inv1, w1z = conv_w[o1*W_COLS+2]*inv1;
    float bb0 = beta[o0] - mean[o0]*inv0;
    float bb1 = beta[o1] - mean[o1]*inv1;

    // lane's neighbor
    int jk = g_idx[pidx*K_ + lane];
    const float* qc = coords + (b*N_ + i)*3;
    float qx = qc[0], qy = qc[1], qz = qc[2];
    const float* gc = coords + (b*N_ + jk)*3;
    float rx = (gc[0] - qx) / 0.2f;
    float ry = (gc[1] - qy) / 0.2f;
    float rz = (gc[2] - qz) / 0.2f;

    // density: streaming top-16 smallest pairwise d2 (rel space; scale later)
    float s[16];
    #pragma unroll
    for (int m = 0; m < 16; m++) s[m] = CUDART_INF_F;
    #pragma unroll
    for (int j = 0; j < K_; j++) {
        float ox = __shfl_sync(0xffffffffu, rx, j);
        float oy = __shfl_sync(0xffffffffu, ry, j);
        float oz = __shfl_sync(0xffffffffu, rz, j);
        float dx = ox - rx, dy = oy - ry, dz = oz - rz;
        float v = dx*dx + dy*dy + dz*dz;
        if (j == lane) v = CUDART_INF_F;   // mask diagonal
        #pragma unroll
        for (int m = 0; m < 16; m++) {     // sorted-insert carry chain
            float lo = fminf(s[m], v);
            v = fmaxf(s[m], v);
            s[m] = lo;
        }
    }
    float kth = sqrtf(s[15]) * 0.2f;       // back to absolute units
    float raw = fmaxf(kth, 1e-8f);
    raw = raw * raw * raw;
    float sum = raw;
    #pragma unroll
    for (int off = 16; off; off >>= 1) sum += __shfl_xor_sync(0xffffffffu, sum, off);
    float w = raw / fmaxf(sum, 1e-8f);

    // weighted accumulation over 32 neighbors; coalesced Gt gathers
    const float* Gb = g_Gt + (b*N_)*C_;
    float acc0 = 0.f, acc1 = 0.f;
    #pragma unroll 4
    for (int k = 0; k < K_; k++) {
        int   jn = __shfl_sync(0xffffffffu, jk, k);
        float wk = __shfl_sync(0xffffffffu, w,  k);
        float ax = __shfl_sync(0xffffffffu, rx, k);
        float ay = __shfl_sync(0xffffffffu, ry, k);
        float az = __shfl_sync(0xffffffffu, rz, k);
        float g0 = Gb[jn*C_ + o0];
        float g1 = Gb[jn*C_ + o1];
        float v0 = fmaf(w0z, az, fmaf(w0y, ay, fmaf(w0x, ax, g0 + bb0)));
        float v1 = fmaf(w1z, az, fmaf(w1y, ay, fmaf(w1x, ax, g1 + bb1)));
        v0 = fmaxf(v0, 0.f);
        v1 = fmaxf(v1, 0.f);
        acc0 = fmaf(wk, v0, acc0);
        acc1 = fmaf(wk, v1, acc1);
    }
    out[(b*C_ + o0)*N_ + i] = acc0;
    out[(b*C_ + o1)*N_ + i] = acc1;
}

extern "C" void kernel_launch(void* const* d_in, const int* in_sizes, int n_in,
                              void* d_out, int out_size) {
    const float* coords = (const float*)d_in[0];
    const float* feats  = (const float*)d_in[1];
    const float* conv_w = (const float*)d_in[2];
    const float* gamma  = (const float*)d_in[3];
    const float* beta   = (const float*)d_in[4];
    const float* mean   = (const float*)d_in[5];
    const float* var    = (const float*)d_in[6];
    float* out = (float*)d_out;

    kA<<<dim3(B_, N_/64), 256>>>(feats, conv_w, gamma, var);
    kB<<<B_*N_/16, 512>>>(coords);
    kC<<<B_*N_/8, 256>>>(coords, conv_w, gamma, beta, mean, var, out);
}

// round 3
// speedup vs baseline: 1.5611x; 1.5611x over previous
#include <cuda_runtime.h>
#include <math_constants.h>

#define B_ 8
#define N_ 2048
#define C_ 64
#define K_ 32
#define W_COLS 67   // C + 3
#define FULL 0xffffffffu

// Scratch (allocation-free rule: device globals)
__device__ __align__(16) float g_Gt[B_*N_*C_];   // (b, n, o): inv[o] * (W_f @ feats)[o,n]
__device__ int g_idx[B_*N_*K_];

// ---------------------------------------------------------------------------
// Fused kernel AB: blocks [0, 128) do the Gt precompute (kA path, launched
// first so it overlaps kB's first wave); blocks [128, 128+1024) do kNN (kB).
// Both paths alias one 48KB static smem buffer.
//
// kB distance REPLICATES the reference cdist rounding exactly:
//   sq   = ((x*x + y*y) + z*z)            (plain mul/add)
//   dot  = fma(z,z', fma(y,y', x*x'))     (ascending fma chain)
//   d2   = max((sq_i + sq_j) - 2*dot, 0)
// Selection: top-32 by (d2, idx) lexicographic (matches stable top_k).
// ---------------------------------------------------------------------------
#define KA_BLOCKS 128
__global__ __launch_bounds__(512) void kAB(const float* __restrict__ coords,
                                           const float* __restrict__ feats,
                                           const float* __restrict__ conv_w,
                                           const float* __restrict__ gamma,
                                           const float* __restrict__ var) {
    __shared__ __align__(16) float sbuf[12288];   // 48 KB
    int bid = blockIdx.x;
    int t = threadIdx.x;

    if (bid < KA_BLOCKS) {
        // ---------------- kA path: Gt[b][n][o] = inv[o]*(W_f @ feats)[o][n]
        float (*sW)[C_]  = (float(*)[C_])sbuf;            // [c][o] 16KB
        float (*sF)[128] = (float(*)[128])(sbuf + 4096);  // [c][n] 32KB
        int b  = bid >> 4;
        int n0 = (bid & 15) * 128;

        for (int x = t; x < C_*C_; x += 512) {
            int o = x & 63, c = x >> 6;
            float inv = gamma[o] * rsqrtf(var[o] + 1e-5f);
            sW[c][o] = conv_w[o*W_COLS + 3 + c] * inv;
        }
        for (int x = t; x < C_*128; x += 512) {
            int c = x >> 7, n = x & 127;
            sF[c][n] = feats[(b*C_ + c)*N_ + n0 + n];
        }
        __syncthreads();

        int oT = (t & 15) * 4;    // 16 o-tiles of 4
        int nT = (t >> 4) * 4;    // 32 n-tiles of 4
        float acc[4][4] = {};
        #pragma unroll 8
        for (int c = 0; c < C_; c++) {
            float w0 = sW[c][oT+0], w1 = sW[c][oT+1], w2 = sW[c][oT+2], w3 = sW[c][oT+3];
            #pragma unroll
            for (int j = 0; j < 4; j++) {
                float f = sF[c][nT+j];
                acc[j][0] = fmaf(w0, f, acc[j][0]);
                acc[j][1] = fmaf(w1, f, acc[j][1]);
                acc[j][2] = fmaf(w2, f, acc[j][2]);
                acc[j][3] = fmaf(w3, f, acc[j][3]);
            }
        }
        #pragma unroll
        for (int j = 0; j < 4; j++) {
            float4 v = make_float4(acc[j][0], acc[j][1], acc[j][2], acc[j][3]);
            *reinterpret_cast<float4*>(&g_Gt[((b*N_) + n0 + nT + j)*C_ + oT]) = v;
        }
        return;
    }

    // ---------------- kB path: exact kNN (K=32), warp-per-query
    {
        float4* sC = (float4*)sbuf;    // 32KB: coords + precomputed sq in .w
        int kb = bid - KA_BLOCKS;
        int warp = t >> 5, lane = t & 31;
        int b = kb >> 7;                        // 128 blocks per batch
        int i = ((kb & 127) << 4) + warp;       // query index

        for (int x = t; x < N_; x += 512) {
            const float* c = coords + (b*N_ + x)*3;
            float cx = c[0], cy = c[1], cz = c[2];
            float sq = __fadd_rn(__fadd_rn(__fmul_rn(cx,cx), __fmul_rn(cy,cy)),
                                 __fmul_rn(cz,cz));
            sC[x] = make_float4(cx, cy, cz, sq);
        }
        __syncthreads();

        float4 q = sC[i];

        auto refd2 = [&](const float4& p) -> float {
            float dot = __fmaf_rn(q.z, p.z, __fmaf_rn(q.y, p.y, __fmul_rn(q.x, p.x)));
            float d2  = __fsub_rn(__fadd_rn(q.w, p.w), __fmul_rn(2.0f, dot));
            return fmaxf(d2, 0.0f);
        };

        // init set with first 32 candidates; one element per lane, unordered
        float bd = refd2(sC[lane]);
        int   bi = lane;

        float md = bd;   // warp-uniform running max of the set (value only)
        #pragma unroll
        for (int off = 16; off; off >>= 1)
            md = fmaxf(md, __shfl_xor_sync(FULL, md, off));

        for (int tt = 32; tt < N_; tt += 32) {
            float d2 = refd2(sC[tt + lane]);
            unsigned m = __ballot_sync(FULL, d2 <= md);
            while (m) {   // warp-uniform serial insertion
                int src = __ffs(m) - 1;
                m &= m - 1;
                float cd = __shfl_sync(FULL, d2, src);
                if (cd > md) continue;           // stale (md tightened)
                int cj = tt + src;

                unsigned hmask = __ballot_sync(FULL, bd == md);
                if (cd == md || (hmask & (hmask - 1))) {
                    // cold path (bit-exact ties): exact (d2, idx) semantics.
                    // mimax = largest index among current-max holders.
                    int tb = (bd == md) ? bi : -1;
                    #pragma unroll
                    for (int off = 16; off; off >>= 1)
                        tb = max(tb, __shfl_xor_sync(FULL, tb, off));
                    if (cd == md && cj >= tb) continue;   // not better than worst incumbent
                    if (bd == md && bi == tb) { bd = cd; bi = cj; }   // evict worst
                } else {
                    if (lane == __ffs(hmask) - 1) { bd = cd; bi = cj; }
                }

                // recompute running max (5 shfl + 5 fmax)
                float tm = bd;
                #pragma unroll
                for (int off = 16; off; off >>= 1)
                    tm = fmaxf(tm, __shfl_xor_sync(FULL, tm, off));
                md = tm;
            }
        }
        g_idx[(b*N_ + i)*K_ + lane] = bi;
    }
}

// ---------------------------------------------------------------------------
// Kernel C: per point (warp-per-point):
//   rel_k = (coords[idx_k] - coords[i]) / R
//   density: 16th-smallest pairwise dist among the 32 grouped points
//   out[o,i] = sum_k w_k * relu(Gt[idx_k][o] + Wrel'[o]·rel_k + bias'[o])
// ---------------------------------------------------------------------------
__global__ __launch_bounds__(256) void kC(const float* __restrict__ coords,
                                          const float* __restrict__ conv_w,
                                          const float* __restrict__ gamma,
                                          const float* __restrict__ beta,
                                          const float* __restrict__ mean,
                                          const float* __restrict__ var,
                                          float* __restrict__ out) {
    int t = threadIdx.x;
    int warp = t >> 5, lane = t & 31;
    int pidx = blockIdx.x * 8 + warp;
    int b = pidx >> 11;
    int i = pidx & (N_ - 1);

    // per-lane channel constants (o0 = lane, o1 = lane + 32), BN folded
    int o0 = lane, o1 = lane + 32;
    float inv0 = gamma[o0] * rsqrtf(var[o0] + 1e-5f);
    float inv1 = gamma[o1] * rsqrtf(var[o1] + 1e-5f);
    float w0x = conv_w[o0*W_COLS+0]*inv0, w0y = conv_w[o0*W_COLS+1]*inv0, w0z = conv_w[o0*W_COLS+2]*inv0;
    float w1x = conv_w[o1*W_COLS+0]*inv1, w1y = conv_w[o1*W_COLS+1]*inv1, w1z = conv_w[o1*W_COLS+2]*inv1;
    float bb0 = beta[o0] - mean[o0]*inv0;
    float bb1 = beta[o1] - mean[o1]*inv1;

    // lane's neighbor
    int jk = g_idx[pidx*K_ + lane];
    const float* qc = coords + (b*N_ + i)*3;
    float qx = qc[0], qy = qc[1], qz = qc[2];
    const float* gc = coords + (b*N_ + jk)*3;
    float rx = (gc[0] - qx) / 0.2f;
    float ry = (gc[1] - qy) / 0.2f;
    float rz = (gc[2] - qz) / 0.2f;

    // density: streaming top-16 smallest pairwise d2 (rel space; scale later)
    float s[16];
    #pragma unroll
    for (int m = 0; m < 16; m++) s[m] = CUDART_INF_F;
    #pragma unroll
    for (int j = 0; j < K_; j++) {
        float ox = __shfl_sync(FULL, rx, j);
        float oy = __shfl_sync(FULL, ry, j);
        float oz = __shfl_sync(FULL, rz, j);
        float dx = ox - rx, dy = oy - ry, dz = oz - rz;
        float v = dx*dx + dy*dy + dz*dz;
        if (j == lane) v = CUDART_INF_F;   // mask diagonal
        #pragma unroll
        for (int m = 0; m < 16; m++) {     // sorted-insert carry chain
            float lo = fminf(s[m], v);
            v = fmaxf(s[m], v);
            s[m] = lo;
        }
    }
    float kth = sqrtf(s[15]) * 0.2f;       // back to absolute units
    float raw = fmaxf(kth, 1e-8f);
    raw = raw * raw * raw;
    float sum = raw;
    #pragma unroll
    for (int off = 16; off; off >>= 1) sum += __shfl_xor_sync(FULL, sum, off);
    float w = raw / fmaxf(sum, 1e-8f);

    // weighted accumulation over 32 neighbors; coalesced Gt gathers
    const float* Gb = g_Gt + (b*N_)*C_;
    float acc0 = 0.f, acc1 = 0.f;
    #pragma unroll 4
    for (int k = 0; k < K_; k++) {
        int   jn = __shfl_sync(FULL, jk, k);
        float wk = __shfl_sync(FULL, w,  k);
        float ax = __shfl_sync(FULL, rx, k);
        float ay = __shfl_sync(FULL, ry, k);
        float az = __shfl_sync(FULL, rz, k);
        float g0 = Gb[jn*C_ + o0];
        float g1 = Gb[jn*C_ + o1];
        float v0 = fmaf(w0z, az, fmaf(w0y, ay, fmaf(w0x, ax, g0 + bb0)));
        float v1 = fmaf(w1z, az, fmaf(w1y, ay, fmaf(w1x, ax, g1 + bb1)));
        v0 = fmaxf(v0, 0.f);
        v1 = fmaxf(v1, 0.f);
        acc0 = fmaf(wk, v0, acc0);
        acc1 = fmaf(wk, v1, acc1);
    }
    out[(b*C_ + o0)*N_ + i] = acc0;
    out[(b*C_ + o1)*N_ + i] = acc1;
}

extern "C" void kernel_launch(void* const* d_in, const int* in_sizes, int n_in,
                              void* d_out, int out_size) {
    const float* coords = (const float*)d_in[0];
    const float* feats  = (const float*)d_in[1];
    const float* conv_w = (const float*)d_in[2];
    const float* gamma  = (const float*)d_in[3];
    const float* beta   = (const float*)d_in[4];
    const float* mean   = (const float*)d_in[5];
    const float* var    = (const float*)d_in[6];
    float* out = (float*)d_out;

    kAB<<<KA_BLOCKS + B_*N_/16, 512>>>(coords, feats, conv_w, gamma, var);
    kC<<<B_*N_/8, 256>>>(coords, conv_w, gamma, beta, mean, var, out);
}

// round 4
// speedup vs baseline: 2.0282x; 1.2992x over previous
#include <cuda_runtime.h>
#include <math_constants.h>

#define B_ 8
#define N_ 2048
#define C_ 64
#define K_ 32
#define W_COLS 67   // C + 3
#define FULL 0xffffffffu

// Scratch (allocation-free rule: device globals)
__device__ __align__(16) float g_Gt[B_*N_*C_];   // (b, n, o): inv[o] * (W_f @ feats)[o,n]
__device__ int g_idx[B_*N_*K_];

// ---------------------------------------------------------------------------
// Fused kernel AB: blocks [0,128) = Gt precompute (kA), blocks [128,1152) = kNN.
// kB distance REPLICATES the reference cdist rounding exactly:
//   sq  = ((x*x + y*y) + z*z)           (plain mul/add)
//   dot = fma(z,z', fma(y,y', x*x'))    (ascending fma chain)
//   d2  = max((sq_i + sq_j) - 2*dot, 0)
// Selection: top-32 by (d2, idx) lexicographic (matches stable top_k).
// ---------------------------------------------------------------------------
#define KA_BLOCKS 128
__global__ __launch_bounds__(512) void kAB(const float* __restrict__ coords,
                                           const float* __restrict__ feats,
                                           const float* __restrict__ conv_w,
                                           const float* __restrict__ gamma,
                                           const float* __restrict__ var) {
    __shared__ __align__(16) float sbuf[12288];   // 48 KB
    int bid = blockIdx.x;
    int t = threadIdx.x;

    if (bid < KA_BLOCKS) {
        // ---------------- kA path
        float (*sW)[C_]  = (float(*)[C_])sbuf;            // [c][o] 16KB
        float (*sF)[128] = (float(*)[128])(sbuf + 4096);  // [c][n] 32KB
        int b  = bid >> 4;
        int n0 = (bid & 15) * 128;

        for (int x = t; x < C_*C_; x += 512) {
            int o = x & 63, c = x >> 6;
            float inv = gamma[o] * rsqrtf(var[o] + 1e-5f);
            sW[c][o] = conv_w[o*W_COLS + 3 + c] * inv;
        }
        for (int x = t; x < C_*128; x += 512) {
            int c = x >> 7, n = x & 127;
            sF[c][n] = feats[(b*C_ + c)*N_ + n0 + n];
        }
        __syncthreads();

        int oT = (t & 15) * 4;
        int nT = (t >> 4) * 4;
        float acc[4][4] = {};
        #pragma unroll 8
        for (int c = 0; c < C_; c++) {
            float w0 = sW[c][oT+0], w1 = sW[c][oT+1], w2 = sW[c][oT+2], w3 = sW[c][oT+3];
            #pragma unroll
            for (int j = 0; j < 4; j++) {
                float f = sF[c][nT+j];
                acc[j][0] = fmaf(w0, f, acc[j][0]);
                acc[j][1] = fmaf(w1, f, acc[j][1]);
                acc[j][2] = fmaf(w2, f, acc[j][2]);
                acc[j][3] = fmaf(w3, f, acc[j][3]);
            }
        }
        #pragma unroll
        for (int j = 0; j < 4; j++) {
            float4 v = make_float4(acc[j][0], acc[j][1], acc[j][2], acc[j][3]);
            *reinterpret_cast<float4*>(&g_Gt[((b*N_) + n0 + nT + j)*C_ + oT]) = v;
        }
        return;
    }

    // ---------------- kB path: exact kNN (K=32), warp-per-query
    {
        float4* sC = (float4*)sbuf;    // 32KB: coords + precomputed sq in .w
        int kb = bid - KA_BLOCKS;
        int warp = t >> 5, lane = t & 31;
        int b = kb >> 7;                        // 128 blocks per batch
        int i = ((kb & 127) << 4) + warp;       // query index

        for (int x = t; x < N_; x += 512) {
            const float* c = coords + (b*N_ + x)*3;
            float cx = c[0], cy = c[1], cz = c[2];
            float sq = __fadd_rn(__fadd_rn(__fmul_rn(cx,cx), __fmul_rn(cy,cy)),
                                 __fmul_rn(cz,cz));
            sC[x] = make_float4(cx, cy, cz, sq);
        }
        __syncthreads();

        float4 q = sC[i];

        auto refd2 = [&](const float4& p) -> float {
            float dot = __fmaf_rn(q.z, p.z, __fmaf_rn(q.y, p.y, __fmul_rn(q.x, p.x)));
            float d2  = __fsub_rn(__fadd_rn(q.w, p.w), __fmul_rn(2.0f, dot));
            return fmaxf(d2, 0.0f);
        };

        // ---- Pass 1: provable upper bound md0 on the 32nd smallest d2.
        // Each lane takes min over its disjoint 64-candidate hand; every lane
        // then owns >=1 element <= max-of-minima => >=32 elements <= md0.
        float lmin = CUDART_INF_F;
        #pragma unroll 4
        for (int it = 0; it < N_/32; it++)
            lmin = fminf(lmin, refd2(sC[it*32 + lane]));
        float md0 = lmin;
        #pragma unroll
        for (int off = 16; off; off >>= 1)
            md0 = fmaxf(md0, __shfl_xor_sync(FULL, md0, off));

        // ---- Init: first 32 candidates, bitonic-sorted ascending by (d2, idx)
        float bd = refd2(sC[lane]);
        int   bi = lane;
        #pragma unroll
        for (int k = 2; k <= 32; k <<= 1) {
            #pragma unroll
            for (int j = k >> 1; j > 0; j >>= 1) {
                float od = __shfl_xor_sync(FULL, bd, j);
                int   oi = __shfl_xor_sync(FULL, bi, j);
                bool up       = ((lane & k) == 0);
                bool keep_min = (((lane & j) == 0) == up);
                bool less     = (od < bd) || (od == bd && oi < bi);
                bool take     = keep_min ? less : !less;   // pairs unique
                if (take) { bd = od; bi = oi; }
            }
        }
        float md = __shfl_sync(FULL, bd, 31);   // current worst of set
        int   mi = __shfl_sync(FULL, bi, 31);

        // ---- Pass 2: filtered scan + sorted-lane insertion
        for (int tt = 32; tt < N_; tt += 32) {
            int jj = tt + lane;
            float d2 = refd2(sC[jj]);
            bool beat = (d2 <= md0) &&
                        ((d2 < md) || (d2 == md && jj < mi));
            unsigned m = __ballot_sync(FULL, beat);
            while (m) {    // warp-uniform serial insertion
                int src = __ffs(m) - 1;
                m &= m - 1;
                float cd = __shfl_sync(FULL, d2, src);
                int   cj = tt + src;
                if (!((cd < md) || (cd == md && cj < mi))) continue;  // stale

                float p_bd = __shfl_up_sync(FULL, bd, 1);
                int   p_bi = __shfl_up_sync(FULL, bi, 1);
                bool gt_self = (bd > cd) || (bd == cd && bi > cj);
                bool gt_prev = (lane > 0) &&
                               ((p_bd > cd) || (p_bd == cd && p_bi > cj));
                if (gt_self) {
                    bd = gt_prev ? p_bd : cd;
                    bi = gt_prev ? p_bi : cj;
                }
                md = __shfl_sync(FULL, bd, 31);
                mi = __shfl_sync(FULL, bi, 31);
            }
        }
        g_idx[(b*N_ + i)*K_ + lane] = bi;
    }
}

// ---------------------------------------------------------------------------
// Kernel C: per point (warp-per-point):
//   rel_k = (coords[idx_k] - coords[i]) / R
//   density: 16th-smallest pairwise dist among the 32 grouped points
//   out[o,i] = sum_k w_k * relu(Gt[idx_k][o] + Wrel'[o]·rel_k + bias'[o])
// Cross-lane values staged in smem; all-lanes-same-address LDS = broadcast.
// ---------------------------------------------------------------------------
__global__ __launch_bounds__(256) void kC(const float* __restrict__ coords,
                                          const float* __restrict__ conv_w,
                                          const float* __restrict__ gamma,
                                          const float* __restrict__ beta,
                                          const float* __restrict__ mean,
                                          const float* __restrict__ var,
                                          float* __restrict__ out) {
    __shared__ __align__(16) float4 sRel[8][K_];   // (rx,ry,rz,w) per neighbor
    __shared__ int sJn[8][K_];
    int t = threadIdx.x;
    int warp = t >> 5, lane = t & 31;
    int pidx = blockIdx.x * 8 + warp;
    int b = pidx >> 11;
    int i = pidx & (N_ - 1);

    // per-lane channel constants (o0 = lane, o1 = lane + 32), BN folded
    int o0 = lane, o1 = lane + 32;
    float inv0 = gamma[o0] * rsqrtf(var[o0] + 1e-5f);
    float inv1 = gamma[o1] * rsqrtf(var[o1] + 1e-5f);
    float w0x = conv_w[o0*W_COLS+0]*inv0, w0y = conv_w[o0*W_COLS+1]*inv0, w0z = conv_w[o0*W_COLS+2]*inv0;
    float w1x = conv_w[o1*W_COLS+0]*inv1, w1y = conv_w[o1*W_COLS+1]*inv1, w1z = conv_w[o1*W_COLS+2]*inv1;
    float bb0 = beta[o0] - mean[o0]*inv0;
    float bb1 = beta[o1] - mean[o1]*inv1;

    // lane's neighbor -> rel coords, staged to smem
    int jk = g_idx[pidx*K_ + lane];
    const float* qc = coords + (b*N_ + i)*3;
    float qx = qc[0], qy = qc[1], qz = qc[2];
    const float* gc = coords + (b*N_ + jk)*3;
    float rx = (gc[0] - qx) / 0.2f;
    float ry = (gc[1] - qy) / 0.2f;
    float rz = (gc[2] - qz) / 0.2f;
    sRel[warp][lane] = make_float4(rx, ry, rz, 0.f);
    sJn[warp][lane] = jk;
    __syncwarp();

    // density: streaming top-16 smallest pairwise d2 (rel space; scale later)
    float s[16];
    #pragma unroll
    for (int m = 0; m < 16; m++) s[m] = CUDART_INF_F;
    #pragma unroll
    for (int j = 0; j < K_; j++) {
        float4 o = sRel[warp][j];                 // LDS broadcast
        float dx = o.x - rx, dy = o.y - ry, dz = o.z - rz;
        float v = dx*dx + dy*dy + dz*dz;
        if (j == lane) v = CUDART_INF_F;          // mask diagonal
        #pragma unroll
        for (int m = 0; m < 16; m++) {            // sorted-insert carry chain
            float lo = fminf(s[m], v);
            v = fmaxf(s[m], v);
            s[m] = lo;
        }
    }
    float kth = sqrtf(s[15]) * 0.2f;              // back to absolute units
    float raw = fmaxf(kth, 1e-8f);
    raw = raw * raw * raw;
    float sum = raw;
    #pragma unroll
    for (int off = 16; off; off >>= 1) sum += __shfl_xor_sync(FULL, sum, off);
    float w = raw / fmaxf(sum, 1e-8f);
    sRel[warp][lane].w = w;
    __syncwarp();

    // weighted accumulation over 32 neighbors; coalesced Gt gathers
    const float* Gb = g_Gt + (b*N_)*C_;
    float acc0 = 0.f, acc1 = 0.f;
    #pragma unroll 4
    for (int k = 0; k < K_; k++) {
        float4 r4 = sRel[warp][k];                // LDS.128 broadcast
        int    jn = sJn[warp][k];
        float g0 = Gb[jn*C_ + o0];
        float g1 = Gb[jn*C_ + o1];
        float v0 = fmaf(w0z, r4.z, fmaf(w0y, r4.y, fmaf(w0x, r4.x, g0 + bb0)));
        float v1 = fmaf(w1z, r4.z, fmaf(w1y, r4.y, fmaf(w1x, r4.x, g1 + bb1)));
        v0 = fmaxf(v0, 0.f);
        v1 = fmaxf(v1, 0.f);
        acc0 = fmaf(r4.w, v0, acc0);
        acc1 = fmaf(r4.w, v1, acc1);
    }
    out[(b*C_ + o0)*N_ + i] = acc0;
    out[(b*C_ + o1)*N_ + i] = acc1;
}

extern "C" void kernel_launch(void* const* d_in, const int* in_sizes, int n_in,
                              void* d_out, int out_size) {
    const float* coords = (const float*)d_in[0];
    const float* feats  = (const float*)d_in[1];
    const float* conv_w = (const float*)d_in[2];
    const float* gamma  = (const float*)d_in[3];
    const float* beta   = (const float*)d_in[4];
    const float* mean   = (const float*)d_in[5];
    const float* var    = (const float*)d_in[6];
    float* out = (float*)d_out;

    kAB<<<KA_BLOCKS + B_*N_/16, 512>>>(coords, feats, conv_w, gamma, var);
    kC<<<B_*N_/8, 256>>>(coords, conv_w, gamma, beta, mean, var, out);
}